// round 10
// baseline (speedup 1.0000x reference)
#include <cuda_runtime.h>
#include <cstdint>
#include <math.h>

// Problem constants (fixed shapes)
#define B_   4
#define C_   64
#define H_   282
#define W_   282
#define P_   12000
#define HW_  (H_ * W_)        // 79524 cells per channel image
#define NQ_  (HW_ / 4)        // 19881 float4-quads per channel image
#define TILES_ 311            // ceil(NQ_/64): 64-quad (256-cell) tiles per batch
#define WGPB_ (TILES_ * 8)    // 2488 warp-groups per batch (8 cg per tile)
#define GW_   (B_ * WGPB_)    // 9952 gather warps
#define GBLK_ (GW_ / 4)       // 2488 blocks of 4 warps

#define PT_  (P_ / 32)        // 375 pillar tiles (exact)
#define CT_  (C_ / 32)        // 2  channel tiles
#define TRANS_BLOCKS_ (B_ * PT_ * CT_)            // 3000
#define IDX_BLOCKS_   ((B_ * P_ + 255) / 256)     // 188

// Scratch (device globals; zero-initialized at module load)
__device__ __align__(16) int   g_winner[B_ * HW_];   // (p+1) of winning pillar, 0 = empty
__device__ __align__(16) float g_tf[B_ * P_ * C_];   // feats transposed to (B, P, C)

__device__ __forceinline__ uint32_t smem_u32(const void* p) {
    return (uint32_t)__cvta_generic_to_shared(p);
}

// ---------------------------------------------------------------------------
// Kernel 0: reset winner plane (runs FIRST each call; gather warps share
// winner words read-only now, so in-gather self-reset would race).
// ---------------------------------------------------------------------------
__global__ void k_reset() {
    int i = blockIdx.x * blockDim.x + threadIdx.x;
    if (i < (B_ * HW_) / 4) ((int4*)g_winner)[i] = make_int4(0, 0, 0, 0);
}

// ---------------------------------------------------------------------------
// Kernel 1 (fused): blocks [0, 3000) transpose feats (B,C,P) -> g_tf (B,P,C)
// via 32x32 smem tiles; blocks [3000, 3188) compute per-pillar cells and
// atomicMax(p+1) into g_winner (sequential last-update-wins == max p).
// Index math matches XLA fast-math lowering: (x + 22) * 6.25f (bit-verified).
// ---------------------------------------------------------------------------
__global__ void k_prep(const float* __restrict__ feats,
                       const float* __restrict__ pin) {
    if (blockIdx.x < TRANS_BLOCKS_) {
        __shared__ float tile[32][33];
        int bid   = blockIdx.x;
        int b     = bid / (PT_ * CT_);
        int rem   = bid - b * (PT_ * CT_);
        int ctile = rem / PT_;
        int ptile = rem - ctile * PT_;
        int tx = threadIdx.x & 31;
        int ty = threadIdx.x >> 5;

        const float* src = feats + ((size_t)b * C_ + ctile * 32) * P_ + ptile * 32;
        #pragma unroll
        for (int i = 0; i < 4; i++) {
            int cl = ty + 8 * i;
            tile[cl][tx] = src[(size_t)cl * P_ + tx];
        }
        __syncthreads();
        float* dst = g_tf + ((size_t)b * P_ + ptile * 32) * C_ + ctile * 32;
        #pragma unroll
        for (int i = 0; i < 4; i++) {
            int pl = ty + 8 * i;
            dst[(size_t)pl * C_ + tx] = tile[tx][pl];
        }
    } else {
        int i = (blockIdx.x - TRANS_BLOCKS_) * 256 + threadIdx.x;
        if (i >= B_ * P_) return;
        int b = i / P_;
        int p = i - b * P_;

        float x = pin[(b * 2 + 0) * P_ + p];
        if (x == 0.0f) return;            // invalid pillars dropped (OOB in ref)
        float y = pin[(b * 2 + 1) * P_ + p];

        int xg = (int)floorf(__fmul_rn(__fadd_rn(x, 22.0f), 6.25f));
        int yg = (int)floorf(__fmul_rn(__fadd_rn(y, 22.0f), 6.25f));
        xg = min(max(xg, 0), W_ - 1);
        yg = min(max(yg, 0), H_ - 1);
        atomicMax(&g_winner[b * HW_ + yg * W_ + xg], p + 1);
    }
}

// ---------------------------------------------------------------------------
// Kernel 2: GATHER with TMA-path bulk stores. Warp = (b, 256-cell tile, cg of
// 8 channels); 4 warps/block (warps of one block cover cg 0-3 / 4-7 of the
// SAME tile -> winner reads L1-shared).
//  - 8 rounds: lane reads winner[cell] (coalesced 128B), gathers 2 float4s of
//    its 8-channel slice for filled cells (predicated -> ~4.5 wf/instr),
//    writes 8 scalars to smem rows (lanes consecutive -> conflict-free),
//  - one lane then fires 8 cp.async.bulk 1D stores (1024B each; tail 656B):
//    smem -> out channel rows. Stores bypass L1tex entirely; the SM's L1tex
//    carries only the gather reads (the R4-R9 co-binder is removed).
// ---------------------------------------------------------------------------
__global__ void __launch_bounds__(128) k_gather(float4* __restrict__ out) {
    __shared__ __align__(16) float sm[4][8 * 264];   // 4 warps x 8 rows x 264 (1056B stride)

    int wid  = threadIdx.x >> 5;
    int lane = threadIdx.x & 31;
    int wg   = blockIdx.x * 4 + wid;          // < GW_
    int b    = wg / WGPB_;
    int rem  = wg - b * WGPB_;
    int tile = rem >> 3;
    int cg   = rem & 7;

    int cellbase = tile * 256;
    int ncell  = min(256, HW_ - cellbase);    // tail tile: 164 cells
    int nbytes = ncell * 4;                   // bytes per channel row (mult. of 16)
    float* smw = sm[wid];

    const int*   wp = g_winner + b * HW_ + cellbase;
    const float* tb = g_tf + (size_t)b * P_ * C_ + cg * 8;
    const float4 Z = make_float4(0.f, 0.f, 0.f, 0.f);

    #pragma unroll
    for (int r = 0; r < 8; r++) {
        int ci = lane + 32 * r;               // 0..255
        int w  = (ci < ncell) ? wp[ci] : 0;
        float4 v0 = Z, v1 = Z;
        if (w > 0) {
            const float4* row = (const float4*)(tb + (size_t)(w - 1) * C_);
            v0 = __ldg(row);
            v1 = __ldg(row + 1);
        }
        smw[0 * 264 + ci] = v0.x;
        smw[1 * 264 + ci] = v0.y;
        smw[2 * 264 + ci] = v0.z;
        smw[3 * 264 + ci] = v0.w;
        smw[4 * 264 + ci] = v1.x;
        smw[5 * 264 + ci] = v1.y;
        smw[6 * 264 + ci] = v1.z;
        smw[7 * 264 + ci] = v1.w;
    }
    __syncwarp();
    asm volatile("fence.proxy.async.shared::cta;" ::: "memory");

    if (lane == 0) {
        uint32_t src = smem_u32(smw);
        const float4* dstq = out + (size_t)(b * C_ + cg * 8) * NQ_ + tile * 64;
        #pragma unroll
        for (int ch = 0; ch < 8; ch++) {
            asm volatile(
                "cp.async.bulk.global.shared::cta.bulk_group [%0], [%1], %2;"
                :: "l"(dstq + (size_t)ch * NQ_), "r"(src + ch * 1056), "r"(nbytes)
                : "memory");
        }
        asm volatile("cp.async.bulk.commit_group;" ::: "memory");
        asm volatile("cp.async.bulk.wait_group 0;" ::: "memory");
    }
}

// ---------------------------------------------------------------------------
extern "C" void kernel_launch(void* const* d_in, const int* in_sizes, int n_in,
                              void* d_out, int out_size) {
    const float* pfn_input  = (const float*)d_in[0];   // (4, 2, 12000, 1)
    const float* pfn_output = (const float*)d_in[1];   // (4, 64, 12000)
    float* out = (float*)d_out;                        // (4, 64, 282, 282)

    k_reset <<<((B_ * HW_) / 4 + 255) / 256, 256>>>();
    k_prep  <<<TRANS_BLOCKS_ + IDX_BLOCKS_,  256>>>(pfn_output, pfn_input);
    k_gather<<<GBLK_,                        128>>>((float4*)out);
}